// round 15
// baseline (speedup 1.0000x reference)
#include <cuda_runtime.h>
#include <cuda_bf16.h>
#include <cstdint>

#define CORES   512
#define SLOTS   4
#define SLEN    64
#define PER_CORE (SLOTS * SLEN)          // 256
#define NSLOTS  (CORES * SLOTS)          // 2048 slots per layer
#define VEC_N   (CORES * PER_CORE)       // 131072
#define C_ENTRIES (CORES * SLOTS * CORES * SLOTS)
#define LIST_CAP 4                       // each slot has <=4 sources
#define GRID_MV 592                      // 148 SMs x 4 CTAs (one full wave)
#define MV_TASKS8 (VEC_N / 8)            // 16384 8-row warp tasks
#define GW_STRIDE (GRID_MV * 8)          // 4736 warps

#define CHUNK_F4   2048                  // 32 KB chunk in float4
#define CHUNK_BYTES (CHUNK_F4 * 16)
#define CHUNKS_PER ((C_ENTRIES / 4) / CHUNK_F4)  // 512 per tensor

// Scratch packed so one memset node clears counters + list padding.
struct Scratch {
    int  cnt[2 * NSLOTS];
    int2 lst[2 * NSLOTS * LIST_CAP];     // zero entry = (src 0, weight 0.0f)
};
__device__ Scratch g_s;
__device__ float g_h[VEC_N];
__device__ float g_y1[VEC_N];

// ---------------------------------------------------------------------------
// Bulk-copy compact, layer-1 routing (Ci) ONLY — Cc compaction is fused into
// mv1's tail, where its DRAM bytes join the W stream and its scan hides in
// mv1's spare issue slots. Each CTA bulk-copies one 32 KB chunk into smem,
// then scans it. C layout [I,J,K,L]: float4 index q = ij*512 + k.
// ---------------------------------------------------------------------------
__global__ void __launch_bounds__(256) compact_kernel(
        const float4* __restrict__ C1,
        int* __restrict__ cnt,
        int2* __restrict__ lst) {
    __shared__ alignas(16) float4 buf[CHUNK_F4];
    __shared__ alignas(8) unsigned long long mbar;
    const int tid = threadIdx.x;
    const int c = blockIdx.x;
    const float4* src = C1 + (size_t)c * CHUNK_F4;
    const int q0 = c * CHUNK_F4;

    const uint32_t mb = (uint32_t)__cvta_generic_to_shared(&mbar);
    const uint32_t sb = (uint32_t)__cvta_generic_to_shared(buf);

    if (tid == 0)
        asm volatile("mbarrier.init.shared.b64 [%0], 1;" :: "r"(mb) : "memory");
    __syncthreads();
    if (tid == 0) {
        asm volatile("mbarrier.arrive.expect_tx.shared.b64 _, [%0], %1;"
                     :: "r"(mb), "r"((uint32_t)CHUNK_BYTES) : "memory");
        asm volatile("cp.async.bulk.shared::cta.global.mbarrier::complete_tx::bytes"
                     " [%0], [%1], %2, [%3];"
                     :: "r"(sb), "l"(src), "r"((uint32_t)CHUNK_BYTES), "r"(mb)
                     : "memory");
    }
    {
        uint32_t done;
        asm volatile(
            "{\n\t.reg .pred p;\n\t"
            "mbarrier.try_wait.parity.acquire.cta.shared::cta.b64 p, [%1], %2;\n\t"
            "selp.b32 %0, 1, 0, p;\n\t}"
            : "=r"(done) : "r"(mb), "r"(0u) : "memory");
        while (!done) {
            asm volatile(
                "{\n\t.reg .pred p;\n\t"
                "mbarrier.try_wait.parity.acquire.cta.shared::cta.b64 p, [%1], %2, 0x989680;\n\t"
                "selp.b32 %0, 1, 0, p;\n\t}"
                : "=r"(done) : "r"(mb), "r"(0u) : "memory");
        }
    }

#pragma unroll
    for (int i = 0; i < 8; i++) {
        const int idx = tid + 256 * i;
        float4 v = buf[idx];
        const int q  = q0 + idx;
        const int ij = q >> 9;
        const int k  = q & 511;
        float vals[4] = {v.x, v.y, v.z, v.w};
#pragma unroll
        for (int l = 0; l < 4; l++) {
            if (vals[l] != 0.0f) {
                int s = k * 4 + l;
                int pos = atomicAdd(&cnt[s], 1);
                if (pos < LIST_CAP)
                    lst[s * LIST_CAP + pos] = make_int2(ij, __float_as_int(vals[l]));
            }
        }
    }
    cudaTriggerProgrammaticLaunchCompletion();
}

// ---------------------------------------------------------------------------
// Dispatch gather, count-free (4 fixed entries per slot; padding w=0/src=0).
// ---------------------------------------------------------------------------
__global__ void gather_kernel(const int2* __restrict__ lst,
                              const float4* __restrict__ src4,
                              float4* __restrict__ h4) {
    int idx = blockIdx.x * blockDim.x + threadIdx.x;   // 32768 threads
    int s  = idx >> 4;
    int m4 = idx & 15;
    cudaGridDependencySynchronize();     // wait: lists / y1 visible
    const int4* lp = reinterpret_cast<const int4*>(lst + s * LIST_CAP);
    int4 e01 = lp[0];   // (src0, w0, src1, w1)
    int4 e23 = lp[1];   // (src2, w2, src3, w3)
    float4 v0 = src4[e01.x * 16 + m4];
    float4 v1 = src4[e01.z * 16 + m4];
    float4 v2 = src4[e23.x * 16 + m4];
    float4 v3 = src4[e23.z * 16 + m4];
    float w0 = __int_as_float(e01.y), w1 = __int_as_float(e01.w);
    float w2 = __int_as_float(e23.y), w3 = __int_as_float(e23.w);
    float4 r;
    r.x = w0 * v0.x + w1 * v1.x + w2 * v2.x + w3 * v3.x;
    r.y = w0 * v0.y + w1 * v1.y + w2 * v2.y + w3 * v3.y;
    r.z = w0 * v0.z + w1 * v1.z + w2 * v2.z + w3 * v3.z;
    r.w = w0 * v0.w + w1 * v1.w + w2 * v2.w + w3 * v3.w;
    h4[idx] = r;
    cudaTriggerProgrammaticLaunchCompletion();
}

// ---------------------------------------------------------------------------
// Barrier-free streaming matvec + capped ReLU, 8-row warp tasks, with:
//  - pre-sync L2 prefetch of the first task's W footprint (R13)
//  - optional fused Cc compaction tail (mv1 only): CTAs < CHUNKS_PER each
//    scan one 32 KB Cc chunk after their mv tasks. Its 16 MB joins the
//    DRAM stream; scan/atomics use mv's spare issue slots.
// W per-core layout [j,k,l,m]: row r=(j,l) stride j:16384 l:64; col c=(k,m).
// ---------------------------------------------------------------------------
__global__ void __launch_bounds__(256, 4) mv_kernel(
        const float* __restrict__ W,
        const float* __restrict__ h,
        float* __restrict__ y,
        const float4* __restrict__ C2,     // Cc (mv1) or nullptr (mv2)
        int* __restrict__ cnt2,
        int2* __restrict__ lst2) {
    const int warp = threadIdx.x >> 5, lane = threadIdx.x & 31;
    const int lg  = lane & 7;
    const int sub = lane >> 3;
    const int gw  = blockIdx.x * 8 + warp;

    // --- pre-sync: prefetch first task's W (8KB) into L2 ---
    if (gw < MV_TASKS8) {
        const int core = gw >> 5;
        const int rg   = gw & 31;
        const int j  = rg >> 3;
        const int l0 = (rg << 3) & 63;
        const float* tb = W + ((size_t)core << 16) + (j << 14) + (l0 << 6);
#pragma unroll
        for (int p = 0; p < 2; p++) {
            const int line  = lane + 32 * p;     // 0..63
            const int chunk = line >> 4;         // k-block 0..3
            const int off   = line & 15;         // 128B line within 2KB
            const float* pa = tb + (chunk << 12) + (off << 5);
            asm volatile("prefetch.global.L2 [%0];" :: "l"(pa));
        }
    }

    cudaGridDependencySynchronize();     // wait: h from gather visible

    for (int t = gw; t < MV_TASKS8; t += GW_STRIDE) {
        const int core = t >> 5;
        const int rg   = t & 31;
        const int r0 = (rg << 3) + sub;       // rows r0 and r0+4
        const int r1 = r0 + 4;
        const float* hb = h + (core << 8);

        float4 hv[8];
#pragma unroll
        for (int tt = 0; tt < 8; tt++)
            hv[tt] = *reinterpret_cast<const float4*>(hb + 4 * lg + 32 * tt);

        const float* Wc = W + ((size_t)core << 16);
        const float* rb0 = Wc + ((r0 >> 6) << 14) + ((r0 & 63) << 6);
        const float* rb1 = Wc + ((r1 >> 6) << 14) + ((r1 & 63) << 6);

        float a0 = 0.f, a1 = 0.f;
#pragma unroll
        for (int tt = 0; tt < 8; tt++) {
            const int c = 4 * lg + 32 * tt;
            const int off = ((c >> 6) << 12) + (c & 63);
            float4 w0 = __ldcs(reinterpret_cast<const float4*>(rb0 + off));
            float4 w1 = __ldcs(reinterpret_cast<const float4*>(rb1 + off));
            a0 += w0.x * hv[tt].x + w0.y * hv[tt].y + w0.z * hv[tt].z + w0.w * hv[tt].w;
            a1 += w1.x * hv[tt].x + w1.y * hv[tt].y + w1.z * hv[tt].z + w1.w * hv[tt].w;
        }
        a0 += __shfl_xor_sync(0xffffffffu, a0, 1);
        a1 += __shfl_xor_sync(0xffffffffu, a1, 1);
        a0 += __shfl_xor_sync(0xffffffffu, a0, 2);
        a1 += __shfl_xor_sync(0xffffffffu, a1, 2);
        a0 += __shfl_xor_sync(0xffffffffu, a0, 4);
        a1 += __shfl_xor_sync(0xffffffffu, a1, 4);
        if (lg == 0) {
            y[(core << 8) + r0] = fminf(fmaxf(a0, 0.0f), 10.0f);
            y[(core << 8) + r1] = fminf(fmaxf(a1, 0.0f), 10.0f);
        }
    }

    // --- fused Cc compaction tail (mv1 only) ---
    if (C2 != nullptr && blockIdx.x < CHUNKS_PER) {
        const int tid = threadIdx.x;
        const int q0 = blockIdx.x * CHUNK_F4;
        const float4* src = C2 + (size_t)q0;
#pragma unroll
        for (int i = 0; i < 8; i++) {
            const int idx = tid + 256 * i;
            float4 v = __ldcs(&src[idx]);
            const int q  = q0 + idx;
            const int ij = q >> 9;
            const int k  = q & 511;
            float vals[4] = {v.x, v.y, v.z, v.w};
#pragma unroll
            for (int l = 0; l < 4; l++) {
                if (vals[l] != 0.0f) {
                    int s = k * 4 + l;
                    int pos = atomicAdd(&cnt2[s], 1);
                    if (pos < LIST_CAP)
                        lst2[s * LIST_CAP + pos] =
                            make_int2(ij, __float_as_int(vals[l]));
                }
            }
        }
    }
    cudaTriggerProgrammaticLaunchCompletion();
}

// ---------------------------------------------------------------------------
// PDL launch helper
// ---------------------------------------------------------------------------
template <typename... Args>
static void launch_pdl(void (*kern)(Args...), dim3 grid, dim3 block,
                       Args... args) {
    cudaLaunchConfig_t cfg = {};
    cfg.gridDim = grid;
    cfg.blockDim = block;
    cfg.dynamicSmemBytes = 0;
    cfg.stream = 0;
    cudaLaunchAttribute at[1];
    at[0].id = cudaLaunchAttributeProgrammaticStreamSerialization;
    at[0].val.programmaticStreamSerializationAllowed = 1;
    cfg.attrs = at;
    cfg.numAttrs = 1;
    cudaLaunchKernelEx(&cfg, kern, args...);
}

extern "C" void kernel_launch(void* const* d_in, const int* in_sizes, int n_in,
                              void* d_out, int out_size) {
    const float* x  = (const float*)d_in[0];
    const float* Wi = (const float*)d_in[1];
    const float* Wo = (const float*)d_in[2];
    const float* Ci = (const float*)d_in[3];
    const float* Cc = (const float*)d_in[4];
    float* out = (float*)d_out;

    Scratch* s; cudaGetSymbolAddress((void**)&s, g_s);
    float* h;   cudaGetSymbolAddress((void**)&h,   g_h);
    float* y1;  cudaGetSymbolAddress((void**)&y1,  g_y1);

    int*  cnt  = s->cnt;
    int2* lst  = s->lst;
    int*  cnt2 = cnt + NSLOTS;
    int2* lst2 = lst + NSLOTS * LIST_CAP;

    // One memset clears counters AND list padding (zero = src 0, weight 0.0f)
    cudaMemsetAsync(s, 0, sizeof(Scratch));

    // Ci compaction only (Cc is fused into mv1's tail)
    compact_kernel<<<CHUNKS_PER, 256>>>((const float4*)Ci, cnt, lst);

    // Layer 1 (PDL edges: compact->gather1->mv1; mv1 also compacts Cc)
    launch_pdl(gather_kernel, dim3(256), dim3(128),
               (const int2*)lst, (const float4*)x, (float4*)h);
    launch_pdl(mv_kernel, dim3(GRID_MV), dim3(256),
               (const float*)Wi, (const float*)h, (float*)y1,
               (const float4*)Cc, (int*)cnt2, (int2*)lst2);

    // Layer 2 (PDL edges: mv1->gather2->mv2)
    launch_pdl(gather_kernel, dim3(256), dim3(128),
               (const int2*)lst2, (const float4*)y1, (float4*)h);
    launch_pdl(mv_kernel, dim3(GRID_MV), dim3(256),
               (const float*)Wo, (const float*)h, (float*)out,
               (const float4*)nullptr, (int*)nullptr, (int2*)nullptr);
}

// round 16
// speedup vs baseline: 1.0045x; 1.0045x over previous
#include <cuda_runtime.h>
#include <cuda_bf16.h>
#include <cstdint>

#define CORES   512
#define SLOTS   4
#define SLEN    64
#define PER_CORE (SLOTS * SLEN)          // 256
#define NSLOTS  (CORES * SLOTS)          // 2048 slots per layer
#define VEC_N   (CORES * PER_CORE)       // 131072
#define C_ENTRIES (CORES * SLOTS * CORES * SLOTS)
#define LIST_CAP 4                       // each slot has <=4 sources
#define GRID_MV 592                      // 148 SMs x 4 CTAs (one full wave)
#define MV_TASKS8 (VEC_N / 8)            // 16384 8-row warp tasks
#define GW_STRIDE (GRID_MV * 8)          // 4736 warps

#define CHUNK_F4   2048                  // 32 KB chunk in float4
#define CHUNK_BYTES (CHUNK_F4 * 16)
#define CHUNKS_PER ((C_ENTRIES / 4) / CHUNK_F4)  // 512 per tensor

// Scratch: Cc lists only (Ci is scattered directly into h). One memset
// clears counters + list padding (zero entry = src 0, weight 0.0f).
struct Scratch {
    int  cnt2[NSLOTS];
    int2 lst2[NSLOTS * LIST_CAP];
};
__device__ Scratch g_s;
__device__ float g_h[VEC_N];             // h1 accumulator, then h2
__device__ float g_y1[VEC_N];

// ---------------------------------------------------------------------------
// Bulk-copy compact, both tensors, 1024 CTAs.
//  - Ci half (CTAs < CHUNKS_PER): scatter each nonzero directly into h:
//    h[(k*4+l)*64 + :] += w * x[ij*64 + :]  via red.global.add.f32.
//    (~7.4k nonzeros total -> ~0.06/thread; x reads are L2-hot.)
//  - Cc half: build destination lists for gather2 as before.
// C layout [I,J,K,L]: float4 index q = ij*512 + k (vector over l).
// ---------------------------------------------------------------------------
__global__ void __launch_bounds__(256) compact_kernel(
        const float4* __restrict__ C1,
        const float4* __restrict__ C2,
        const float4* __restrict__ x4,
        float* __restrict__ h,
        int* __restrict__ cnt2,
        int2* __restrict__ lst2) {
    __shared__ alignas(16) float4 buf[CHUNK_F4];
    __shared__ alignas(8) unsigned long long mbar;
    const int tid = threadIdx.x;
    const int chunk = blockIdx.x;
    const bool second = (chunk >= CHUNKS_PER);
    const int c = second ? chunk - CHUNKS_PER : chunk;
    const float4* src = (second ? C2 : C1) + (size_t)c * CHUNK_F4;
    const int q0 = c * CHUNK_F4;

    const uint32_t mb = (uint32_t)__cvta_generic_to_shared(&mbar);
    const uint32_t sb = (uint32_t)__cvta_generic_to_shared(buf);

    if (tid == 0)
        asm volatile("mbarrier.init.shared.b64 [%0], 1;" :: "r"(mb) : "memory");
    __syncthreads();
    if (tid == 0) {
        asm volatile("mbarrier.arrive.expect_tx.shared.b64 _, [%0], %1;"
                     :: "r"(mb), "r"((uint32_t)CHUNK_BYTES) : "memory");
        asm volatile("cp.async.bulk.shared::cta.global.mbarrier::complete_tx::bytes"
                     " [%0], [%1], %2, [%3];"
                     :: "r"(sb), "l"(src), "r"((uint32_t)CHUNK_BYTES), "r"(mb)
                     : "memory");
    }
    {
        uint32_t done;
        asm volatile(
            "{\n\t.reg .pred p;\n\t"
            "mbarrier.try_wait.parity.acquire.cta.shared::cta.b64 p, [%1], %2;\n\t"
            "selp.b32 %0, 1, 0, p;\n\t}"
            : "=r"(done) : "r"(mb), "r"(0u) : "memory");
        while (!done) {
            asm volatile(
                "{\n\t.reg .pred p;\n\t"
                "mbarrier.try_wait.parity.acquire.cta.shared::cta.b64 p, [%1], %2, 0x989680;\n\t"
                "selp.b32 %0, 1, 0, p;\n\t}"
                : "=r"(done) : "r"(mb), "r"(0u) : "memory");
        }
    }

#pragma unroll
    for (int i = 0; i < 8; i++) {
        const int idx = tid + 256 * i;
        float4 v = buf[idx];
        const int q  = q0 + idx;
        const int ij = q >> 9;
        const int k  = q & 511;
        float vals[4] = {v.x, v.y, v.z, v.w};
#pragma unroll
        for (int l = 0; l < 4; l++) {
            if (vals[l] != 0.0f) {
                if (!second) {
                    // Ci: scatter w * x[ij,:] into h[(k,l),:]
                    const float w = vals[l];
                    const float4* xs = x4 + ij * 16;
                    float* hd = h + ((k * 4 + l) << 6);
#pragma unroll 4
                    for (int m4 = 0; m4 < 16; m4++) {
                        float4 xv = __ldg(&xs[m4]);
                        atomicAdd(&hd[m4 * 4 + 0], w * xv.x);
                        atomicAdd(&hd[m4 * 4 + 1], w * xv.y);
                        atomicAdd(&hd[m4 * 4 + 2], w * xv.z);
                        atomicAdd(&hd[m4 * 4 + 3], w * xv.w);
                    }
                } else {
                    // Cc: destination list for gather2
                    int s = k * 4 + l;
                    int pos = atomicAdd(&cnt2[s], 1);
                    if (pos < LIST_CAP)
                        lst2[s * LIST_CAP + pos] =
                            make_int2(ij, __float_as_int(vals[l]));
                }
            }
        }
    }
    cudaTriggerProgrammaticLaunchCompletion();
}

// ---------------------------------------------------------------------------
// Dispatch gather for layer 2, count-free (4 fixed entries per slot; padding
// w=0/src=0). List loads hoisted BEFORE the PDL sync: lst2 was completed by
// compact, which finished before mv1 (our predecessor) even started.
// Only the y1 reads need the sync.
// ---------------------------------------------------------------------------
__global__ void gather_kernel(const int2* __restrict__ lst,
                              const float4* __restrict__ src4,
                              float4* __restrict__ h4) {
    int idx = blockIdx.x * blockDim.x + threadIdx.x;   // 32768 threads
    int s  = idx >> 4;
    int m4 = idx & 15;
    const int4* lp = reinterpret_cast<const int4*>(lst + s * LIST_CAP);
    int4 e01 = lp[0];   // (src0, w0, src1, w1)   pre-sync
    int4 e23 = lp[1];   // (src2, w2, src3, w3)
    cudaGridDependencySynchronize();     // wait: y1 from mv1 visible
    float4 v0 = src4[e01.x * 16 + m4];
    float4 v1 = src4[e01.z * 16 + m4];
    float4 v2 = src4[e23.x * 16 + m4];
    float4 v3 = src4[e23.z * 16 + m4];
    float w0 = __int_as_float(e01.y), w1 = __int_as_float(e01.w);
    float w2 = __int_as_float(e23.y), w3 = __int_as_float(e23.w);
    float4 r;
    r.x = w0 * v0.x + w1 * v1.x + w2 * v2.x + w3 * v3.x;
    r.y = w0 * v0.y + w1 * v1.y + w2 * v2.y + w3 * v3.y;
    r.z = w0 * v0.z + w1 * v1.z + w2 * v2.z + w3 * v3.z;
    r.w = w0 * v0.w + w1 * v1.w + w2 * v2.w + w3 * v3.w;
    h4[idx] = r;
    cudaTriggerProgrammaticLaunchCompletion();
}

// ---------------------------------------------------------------------------
// Barrier-free streaming matvec + capped ReLU, 8-row warp tasks, with
// pre-sync L2 prefetch of the first task's W footprint (R13 version).
// W per-core layout [j,k,l,m]: row r=(j,l) stride j:16384 l:64; col c=(k,m).
// ---------------------------------------------------------------------------
__global__ void __launch_bounds__(256, 4) mv_kernel(
        const float* __restrict__ W,
        const float* __restrict__ h,
        float* __restrict__ y) {
    const int warp = threadIdx.x >> 5, lane = threadIdx.x & 31;
    const int lg  = lane & 7;
    const int sub = lane >> 3;
    const int gw  = blockIdx.x * 8 + warp;

    // --- pre-sync: prefetch first task's W (8KB) into L2 ---
    if (gw < MV_TASKS8) {
        const int core = gw >> 5;
        const int rg   = gw & 31;
        const int j  = rg >> 3;
        const int l0 = (rg << 3) & 63;
        const float* tb = W + ((size_t)core << 16) + (j << 14) + (l0 << 6);
#pragma unroll
        for (int p = 0; p < 2; p++) {
            const int line  = lane + 32 * p;     // 0..63
            const int chunk = line >> 4;         // k-block 0..3
            const int off   = line & 15;         // 128B line within 2KB
            const float* pa = tb + (chunk << 12) + (off << 5);
            asm volatile("prefetch.global.L2 [%0];" :: "l"(pa));
        }
    }

    cudaGridDependencySynchronize();     // wait: h visible

    for (int t = gw; t < MV_TASKS8; t += GW_STRIDE) {
        const int core = t >> 5;
        const int rg   = t & 31;
        const int r0 = (rg << 3) + sub;       // rows r0 and r0+4
        const int r1 = r0 + 4;
        const float* hb = h + (core << 8);

        float4 hv[8];
#pragma unroll
        for (int tt = 0; tt < 8; tt++)
            hv[tt] = *reinterpret_cast<const float4*>(hb + 4 * lg + 32 * tt);

        const float* Wc = W + ((size_t)core << 16);
        const float* rb0 = Wc + ((r0 >> 6) << 14) + ((r0 & 63) << 6);
        const float* rb1 = Wc + ((r1 >> 6) << 14) + ((r1 & 63) << 6);

        float a0 = 0.f, a1 = 0.f;
#pragma unroll
        for (int tt = 0; tt < 8; tt++) {
            const int c = 4 * lg + 32 * tt;
            const int off = ((c >> 6) << 12) + (c & 63);
            float4 w0 = __ldcs(reinterpret_cast<const float4*>(rb0 + off));
            float4 w1 = __ldcs(reinterpret_cast<const float4*>(rb1 + off));
            a0 += w0.x * hv[tt].x + w0.y * hv[tt].y + w0.z * hv[tt].z + w0.w * hv[tt].w;
            a1 += w1.x * hv[tt].x + w1.y * hv[tt].y + w1.z * hv[tt].z + w1.w * hv[tt].w;
        }
        a0 += __shfl_xor_sync(0xffffffffu, a0, 1);
        a1 += __shfl_xor_sync(0xffffffffu, a1, 1);
        a0 += __shfl_xor_sync(0xffffffffu, a0, 2);
        a1 += __shfl_xor_sync(0xffffffffu, a1, 2);
        a0 += __shfl_xor_sync(0xffffffffu, a0, 4);
        a1 += __shfl_xor_sync(0xffffffffu, a1, 4);
        if (lg == 0) {
            y[(core << 8) + r0] = fminf(fmaxf(a0, 0.0f), 10.0f);
            y[(core << 8) + r1] = fminf(fmaxf(a1, 0.0f), 10.0f);
        }
    }
    cudaTriggerProgrammaticLaunchCompletion();
}

// ---------------------------------------------------------------------------
// PDL launch helper
// ---------------------------------------------------------------------------
template <typename... Args>
static void launch_pdl(void (*kern)(Args...), dim3 grid, dim3 block,
                       Args... args) {
    cudaLaunchConfig_t cfg = {};
    cfg.gridDim = grid;
    cfg.blockDim = block;
    cfg.dynamicSmemBytes = 0;
    cfg.stream = 0;
    cudaLaunchAttribute at[1];
    at[0].id = cudaLaunchAttributeProgrammaticStreamSerialization;
    at[0].val.programmaticStreamSerializationAllowed = 1;
    cfg.attrs = at;
    cfg.numAttrs = 1;
    cudaLaunchKernelEx(&cfg, kern, args...);
}

extern "C" void kernel_launch(void* const* d_in, const int* in_sizes, int n_in,
                              void* d_out, int out_size) {
    const float* x  = (const float*)d_in[0];
    const float* Wi = (const float*)d_in[1];
    const float* Wo = (const float*)d_in[2];
    const float* Ci = (const float*)d_in[3];
    const float* Cc = (const float*)d_in[4];
    float* out = (float*)d_out;

    Scratch* s; cudaGetSymbolAddress((void**)&s, g_s);
    float* h;   cudaGetSymbolAddress((void**)&h,   g_h);
    float* y1;  cudaGetSymbolAddress((void**)&y1,  g_y1);

    // Clear Cc lists (padding = src 0 / weight 0.0f) and the h1 accumulator.
    cudaMemsetAsync(s, 0, sizeof(Scratch));
    cudaMemsetAsync(h, 0, VEC_N * sizeof(float));

    // Compact both tensors; Ci half scatters h1 directly.
    compact_kernel<<<2 * CHUNKS_PER, 256>>>(
        (const float4*)Ci, (const float4*)Cc, (const float4*)x,
        h, s->cnt2, s->lst2);

    // Layer 1 (PDL edge: compact->mv1)
    launch_pdl(mv_kernel, dim3(GRID_MV), dim3(256),
               (const float*)Wi, (const float*)h, (float*)y1);

    // Layer 2 (PDL edges: mv1->gather2->mv2)
    launch_pdl(gather_kernel, dim3(256), dim3(128),
               (const int2*)s->lst2, (const float4*)y1, (float4*)h);
    launch_pdl(mv_kernel, dim3(GRID_MV), dim3(256),
               (const float*)Wo, (const float*)h, (float*)out);
}

// round 17
// speedup vs baseline: 1.1958x; 1.1905x over previous
#include <cuda_runtime.h>
#include <cuda_bf16.h>
#include <cstdint>

#define CORES   512
#define SLOTS   4
#define SLEN    64
#define PER_CORE (SLOTS * SLEN)          // 256
#define NSLOTS  (CORES * SLOTS)          // 2048 slots per layer
#define VEC_N   (CORES * PER_CORE)       // 131072
#define C_ENTRIES (CORES * SLOTS * CORES * SLOTS)
#define LIST_CAP 4                       // each slot has <=4 sources
#define GRID_MV 592                      // 148 SMs x 4 CTAs (one full wave)
#define MV_TASKS8 (VEC_N / 8)            // 16384 8-row warp tasks
#define GW_STRIDE (GRID_MV * 8)          // 4736 warps

#define CHUNK_F4   2048                  // 32 KB chunk in float4
#define CHUNK_BYTES (CHUNK_F4 * 16)
#define CHUNKS_PER ((C_ENTRIES / 4) / CHUNK_F4)  // 512 per tensor
#define X_LINES    (VEC_N * 4 / 128)     // 4096 128B lines of x

// Scratch packed so one memset node clears counters + list padding.
struct Scratch {
    int  cnt[2 * NSLOTS];
    int2 lst[2 * NSLOTS * LIST_CAP];     // zero entry = (src 0, weight 0.0f)
};
__device__ Scratch g_s;
__device__ float g_h[VEC_N];
__device__ float g_y1[VEC_N];

// ---------------------------------------------------------------------------
// Bulk-copy compact (R13): each CTA bulk-copies one 32 KB chunk of a routing
// tensor into smem, then scans it. Adds a tiny x prefetch (4096 lines total,
// first 4096 threads) so gather1's x reads hit L2.
// C layout [I,J,K,L]: float4 index q = ij*512 + k (vector over l).
// ---------------------------------------------------------------------------
__global__ void __launch_bounds__(256) compact_kernel(
        const float4* __restrict__ C1,
        const float4* __restrict__ C2,
        const float* __restrict__ x,
        int* __restrict__ cnt,
        int2* __restrict__ lst) {
    __shared__ alignas(16) float4 buf[CHUNK_F4];
    __shared__ alignas(8) unsigned long long mbar;
    const int tid = threadIdx.x;
    const int chunk = blockIdx.x;
    const bool second = (chunk >= CHUNKS_PER);
    const int c = second ? chunk - CHUNKS_PER : chunk;
    const float4* src = (second ? C2 : C1) + (size_t)c * CHUNK_F4;
    int*  cn = second ? cnt + NSLOTS : cnt;
    int2* ls = second ? lst + NSLOTS * LIST_CAP : lst;
    const int q0 = c * CHUNK_F4;

    const uint32_t mb = (uint32_t)__cvta_generic_to_shared(&mbar);
    const uint32_t sb = (uint32_t)__cvta_generic_to_shared(buf);

    if (tid == 0)
        asm volatile("mbarrier.init.shared.b64 [%0], 1;" :: "r"(mb) : "memory");
    __syncthreads();
    if (tid == 0) {
        asm volatile("mbarrier.arrive.expect_tx.shared.b64 _, [%0], %1;"
                     :: "r"(mb), "r"((uint32_t)CHUNK_BYTES) : "memory");
        asm volatile("cp.async.bulk.shared::cta.global.mbarrier::complete_tx::bytes"
                     " [%0], [%1], %2, [%3];"
                     :: "r"(sb), "l"(src), "r"((uint32_t)CHUNK_BYTES), "r"(mb)
                     : "memory");
    }

    // Tiny x prefetch (512 KB total across the whole grid) for gather1.
    {
        const int g = chunk * 256 + tid;
        if (g < X_LINES) {
            const float* pa = x + g * 32;
            asm volatile("prefetch.global.L2 [%0];" :: "l"(pa));
        }
    }

    {
        uint32_t done;
        asm volatile(
            "{\n\t.reg .pred p;\n\t"
            "mbarrier.try_wait.parity.acquire.cta.shared::cta.b64 p, [%1], %2;\n\t"
            "selp.b32 %0, 1, 0, p;\n\t}"
            : "=r"(done) : "r"(mb), "r"(0u) : "memory");
        while (!done) {
            asm volatile(
                "{\n\t.reg .pred p;\n\t"
                "mbarrier.try_wait.parity.acquire.cta.shared::cta.b64 p, [%1], %2, 0x989680;\n\t"
                "selp.b32 %0, 1, 0, p;\n\t}"
                : "=r"(done) : "r"(mb), "r"(0u) : "memory");
        }
    }

#pragma unroll
    for (int i = 0; i < 8; i++) {
        const int idx = tid + 256 * i;
        float4 v = buf[idx];
        const int q  = q0 + idx;
        const int ij = q >> 9;
        const int k  = q & 511;
        float vals[4] = {v.x, v.y, v.z, v.w};
#pragma unroll
        for (int l = 0; l < 4; l++) {
            if (vals[l] != 0.0f) {
                int s = k * 4 + l;
                int pos = atomicAdd(&cn[s], 1);
                if (pos < LIST_CAP)
                    lst[0] = lst[0];  // no-op to keep structure identical
                if (pos < LIST_CAP)
                    ls[s * LIST_CAP + pos] = make_int2(ij, __float_as_int(vals[l]));
            }
        }
    }
    cudaTriggerProgrammaticLaunchCompletion();
}

// ---------------------------------------------------------------------------
// Dispatch gather 1 (R13): lists come from the direct predecessor (compact),
// so all loads stay after the PDL sync.
// ---------------------------------------------------------------------------
__global__ void gather_kernel(const int2* __restrict__ lst,
                              const float4* __restrict__ src4,
                              float4* __restrict__ h4) {
    int idx = blockIdx.x * blockDim.x + threadIdx.x;   // 32768 threads
    int s  = idx >> 4;
    int m4 = idx & 15;
    cudaGridDependencySynchronize();     // wait: compact lists visible
    const int4* lp = reinterpret_cast<const int4*>(lst + s * LIST_CAP);
    int4 e01 = lp[0];   // (src0, w0, src1, w1)
    int4 e23 = lp[1];   // (src2, w2, src3, w3)
    float4 v0 = src4[e01.x * 16 + m4];
    float4 v1 = src4[e01.z * 16 + m4];
    float4 v2 = src4[e23.x * 16 + m4];
    float4 v3 = src4[e23.z * 16 + m4];
    float w0 = __int_as_float(e01.y), w1 = __int_as_float(e01.w);
    float w2 = __int_as_float(e23.y), w3 = __int_as_float(e23.w);
    float4 r;
    r.x = w0 * v0.x + w1 * v1.x + w2 * v2.x + w3 * v3.x;
    r.y = w0 * v0.y + w1 * v1.y + w2 * v2.y + w3 * v3.y;
    r.z = w0 * v0.z + w1 * v1.z + w2 * v2.z + w3 * v3.z;
    r.w = w0 * v0.w + w1 * v1.w + w2 * v2.w + w3 * v3.w;
    h4[idx] = r;
    cudaTriggerProgrammaticLaunchCompletion();
}

// ---------------------------------------------------------------------------
// Dispatch gather 2: lists (lst2) were completed by compact, two kernels
// upstream of our PDL predecessor (mv1) — so the list loads are hoisted
// BEFORE the sync, overlapping mv1's tail and halving the post-sync chain.
// ---------------------------------------------------------------------------
__global__ void gather2_kernel(const int2* __restrict__ lst,
                               const float4* __restrict__ src4,
                               float4* __restrict__ h4) {
    int idx = blockIdx.x * blockDim.x + threadIdx.x;   // 32768 threads
    int s  = idx >> 4;
    int m4 = idx & 15;
    const int4* lp = reinterpret_cast<const int4*>(lst + s * LIST_CAP);
    int4 e01 = lp[0];   // pre-sync: ready since compact
    int4 e23 = lp[1];
    cudaGridDependencySynchronize();     // wait: y1 from mv1 visible
    float4 v0 = src4[e01.x * 16 + m4];
    float4 v1 = src4[e01.z * 16 + m4];
    float4 v2 = src4[e23.x * 16 + m4];
    float4 v3 = src4[e23.z * 16 + m4];
    float w0 = __int_as_float(e01.y), w1 = __int_as_float(e01.w);
    float w2 = __int_as_float(e23.y), w3 = __int_as_float(e23.w);
    float4 r;
    r.x = w0 * v0.x + w1 * v1.x + w2 * v2.x + w3 * v3.x;
    r.y = w0 * v0.y + w1 * v1.y + w2 * v2.y + w3 * v3.y;
    r.z = w0 * v0.z + w1 * v1.z + w2 * v2.z + w3 * v3.z;
    r.w = w0 * v0.w + w1 * v1.w + w2 * v2.w + w3 * v3.w;
    h4[idx] = r;
    cudaTriggerProgrammaticLaunchCompletion();
}

// ---------------------------------------------------------------------------
// Barrier-free streaming matvec + capped ReLU, 8-row warp tasks, with
// pre-sync L2 prefetch of the first task's W footprint (R13 version).
// W per-core layout [j,k,l,m]: row r=(j,l) stride j:16384 l:64; col c=(k,m).
// ---------------------------------------------------------------------------
__global__ void __launch_bounds__(256, 4) mv_kernel(
        const float* __restrict__ W,
        const float* __restrict__ h,
        float* __restrict__ y) {
    const int warp = threadIdx.x >> 5, lane = threadIdx.x & 31;
    const int lg  = lane & 7;
    const int sub = lane >> 3;
    const int gw  = blockIdx.x * 8 + warp;

    // --- pre-sync: prefetch first task's W (8KB) into L2 ---
    if (gw < MV_TASKS8) {
        const int core = gw >> 5;
        const int rg   = gw & 31;
        const int j  = rg >> 3;
        const int l0 = (rg << 3) & 63;
        const float* tb = W + ((size_t)core << 16) + (j << 14) + (l0 << 6);
#pragma unroll
        for (int p = 0; p < 2; p++) {
            const int line  = lane + 32 * p;     // 0..63
            const int chunk = line >> 4;         // k-block 0..3
            const int off   = line & 15;         // 128B line within 2KB
            const float* pa = tb + (chunk << 12) + (off << 5);
            asm volatile("prefetch.global.L2 [%0];" :: "l"(pa));
        }
    }

    cudaGridDependencySynchronize();     // wait: h visible

    for (int t = gw; t < MV_TASKS8; t += GW_STRIDE) {
        const int core = t >> 5;
        const int rg   = t & 31;
        const int r0 = (rg << 3) + sub;       // rows r0 and r0+4
        const int r1 = r0 + 4;
        const float* hb = h + (core << 8);

        float4 hv[8];
#pragma unroll
        for (int tt = 0; tt < 8; tt++)
            hv[tt] = *reinterpret_cast<const float4*>(hb + 4 * lg + 32 * tt);

        const float* Wc = W + ((size_t)core << 16);
        const float* rb0 = Wc + ((r0 >> 6) << 14) + ((r0 & 63) << 6);
        const float* rb1 = Wc + ((r1 >> 6) << 14) + ((r1 & 63) << 6);

        float a0 = 0.f, a1 = 0.f;
#pragma unroll
        for (int tt = 0; tt < 8; tt++) {
            const int c = 4 * lg + 32 * tt;
            const int off = ((c >> 6) << 12) + (c & 63);
            float4 w0 = __ldcs(reinterpret_cast<const float4*>(rb0 + off));
            float4 w1 = __ldcs(reinterpret_cast<const float4*>(rb1 + off));
            a0 += w0.x * hv[tt].x + w0.y * hv[tt].y + w0.z * hv[tt].z + w0.w * hv[tt].w;
            a1 += w1.x * hv[tt].x + w1.y * hv[tt].y + w1.z * hv[tt].z + w1.w * hv[tt].w;
        }
        a0 += __shfl_xor_sync(0xffffffffu, a0, 1);
        a1 += __shfl_xor_sync(0xffffffffu, a1, 1);
        a0 += __shfl_xor_sync(0xffffffffu, a0, 2);
        a1 += __shfl_xor_sync(0xffffffffu, a1, 2);
        a0 += __shfl_xor_sync(0xffffffffu, a0, 4);
        a1 += __shfl_xor_sync(0xffffffffu, a1, 4);
        if (lg == 0) {
            y[(core << 8) + r0] = fminf(fmaxf(a0, 0.0f), 10.0f);
            y[(core << 8) + r1] = fminf(fmaxf(a1, 0.0f), 10.0f);
        }
    }
    cudaTriggerProgrammaticLaunchCompletion();
}

// ---------------------------------------------------------------------------
// PDL launch helper
// ---------------------------------------------------------------------------
template <typename... Args>
static void launch_pdl(void (*kern)(Args...), dim3 grid, dim3 block,
                       Args... args) {
    cudaLaunchConfig_t cfg = {};
    cfg.gridDim = grid;
    cfg.blockDim = block;
    cfg.dynamicSmemBytes = 0;
    cfg.stream = 0;
    cudaLaunchAttribute at[1];
    at[0].id = cudaLaunchAttributeProgrammaticStreamSerialization;
    at[0].val.programmaticStreamSerializationAllowed = 1;
    cfg.attrs = at;
    cfg.numAttrs = 1;
    cudaLaunchKernelEx(&cfg, kern, args...);
}

extern "C" void kernel_launch(void* const* d_in, const int* in_sizes, int n_in,
                              void* d_out, int out_size) {
    const float* x  = (const float*)d_in[0];
    const float* Wi = (const float*)d_in[1];
    const float* Wo = (const float*)d_in[2];
    const float* Ci = (const float*)d_in[3];
    const float* Cc = (const float*)d_in[4];
    float* out = (float*)d_out;

    Scratch* s; cudaGetSymbolAddress((void**)&s, g_s);
    float* h;   cudaGetSymbolAddress((void**)&h,   g_h);
    float* y1;  cudaGetSymbolAddress((void**)&y1,  g_y1);

    int*  cnt = s->cnt;
    int2* lst = s->lst;

    // One memset clears counters AND list padding (zero = src 0, weight 0.0f)
    cudaMemsetAsync(s, 0, sizeof(Scratch));

    compact_kernel<<<2 * CHUNKS_PER, 256>>>((const float4*)Ci, (const float4*)Cc,
                                            x, cnt, lst);

    // Layer 1 (PDL edges: compact->gather1->mv1)
    launch_pdl(gather_kernel, dim3(256), dim3(128),
               (const int2*)lst, (const float4*)x, (float4*)h);
    launch_pdl(mv_kernel, dim3(GRID_MV), dim3(256),
               (const float*)Wi, (const float*)h, (float*)y1);

    // Layer 2 (PDL edges: mv1->gather2->mv2)
    launch_pdl(gather2_kernel, dim3(256), dim3(128),
               (const int2*)(lst + NSLOTS * LIST_CAP), (const float4*)y1,
               (float4*)h);
    launch_pdl(mv_kernel, dim3(GRID_MV), dim3(256),
               (const float*)Wo, (const float*)h, (float*)out);
}